// round 6
// baseline (speedup 1.0000x reference)
#include <cuda_runtime.h>
#include <cstdint>

// GatedBlockParity: N x 2048 fp32 in -> N x 1664 fp32 out
// in row:  [0,256) scalars | [256,640) gates (384) | [640,1408) ns1 (256x3) | [1408,2048) ns2 (128x5)
// out row: [0,256) relu(scalars) | [256,1024) ns1*sig(g1) | [1024,1664) ns2*sig(g2)

static constexpr int IN_W   = 2048;
static constexpr int OUT_W  = 1664;
static constexpr int OUT_W4 = OUT_W / 4;   // 416 float4 per row = 13 warps exactly

__device__ __forceinline__ float sigmoidf_(float x) {
    return 1.0f / (1.0f + __expf(-x));
}

// Each thread processes the SAME column-float4 in FOUR rows: r, r+Q, r+2Q, r+3Q.
// Branch depends only on c -> no divergence; the 4 LDG.128s front-batch (MLP_p1=4).
// Data (read-once) uses __ldcs, stores (write-once) __stcs, leaving L2 capacity
// for the multiply-re-read gate region.
// Within one float4 of a period-p gated block, the 4 lanes touch exactly <=2
// distinct gates (i0=j/p, i0+1): 2 gate loads + 2 sigmoids per row, select by r=j%p.
__global__ __launch_bounds__(256) void gbp_kernel(const float* __restrict__ in,
                                                  float* __restrict__ out,
                                                  int quarter4, int rowsQ) {
    int idx = blockIdx.x * blockDim.x + threadIdx.x;
    if (idx >= quarter4) return;

    int row = idx / OUT_W4;
    int c4  = idx - row * OUT_W4;
    int c   = c4 << 2;

    const float* __restrict__ ip0 = in + (size_t)row * IN_W;
    const size_t istep = (size_t)rowsQ * IN_W;
    float* __restrict__ op0 = out + (size_t)row * OUT_W + c;
    const size_t ostep = (size_t)rowsQ * OUT_W;

    const float* ip[4] = { ip0, ip0 + istep, ip0 + 2 * istep, ip0 + 3 * istep };
    float*       op[4] = { op0, op0 + ostep, op0 + 2 * ostep, op0 + 3 * ostep };

    float4 v[4];

    if (c < 256) {
        // scalars: relu
        #pragma unroll
        for (int k = 0; k < 4; k++)
            v[k] = __ldcs(reinterpret_cast<const float4*>(ip[k] + c));
        #pragma unroll
        for (int k = 0; k < 4; k++) {
            v[k].x = fmaxf(v[k].x, 0.0f); v[k].y = fmaxf(v[k].y, 0.0f);
            v[k].z = fmaxf(v[k].z, 0.0f); v[k].w = fmaxf(v[k].w, 0.0f);
        }
    } else if (c < 1024) {
        // ns1: 256 groups of 3, gated by g1 = in-row[256 + i]
        int j  = c - 256;
        int i0 = j / 3;
        int r  = j - 3 * i0;
        #pragma unroll
        for (int k = 0; k < 4; k++)
            v[k] = __ldcs(reinterpret_cast<const float4*>(ip[k] + 640 + j));
        #pragma unroll
        for (int k = 0; k < 4; k++) {
            float s0 = sigmoidf_(ip[k][256 + i0]);
            float s1 = sigmoidf_(ip[k][256 + i0 + 1]);
            // lane gate idx: x->i0; y->i0+(r==2); z->i0+(r>=1); w->i0+1
            v[k].x *= s0;
            v[k].y *= (r == 2) ? s1 : s0;
            v[k].z *= (r >= 1) ? s1 : s0;
            v[k].w *= s1;
        }
    } else {
        // ns2: 128 groups of 5, gated by g2 = in-row[512 + i]
        int j  = c - 1024;
        int i0 = j / 5;
        int r  = j - 5 * i0;
        #pragma unroll
        for (int k = 0; k < 4; k++)
            v[k] = __ldcs(reinterpret_cast<const float4*>(ip[k] + 1408 + j));
        #pragma unroll
        for (int k = 0; k < 4; k++) {
            float s0 = sigmoidf_(ip[k][512 + i0]);
            float s1 = sigmoidf_(ip[k][512 + i0 + 1]);  // at i0=127 reads ns1[0]; provably unused (r<2)
            // lane gate idx: x->i0; y->i0+(r==4); z->i0+(r>=3); w->i0+(r>=2)
            v[k].x *= s0;
            v[k].y *= (r == 4) ? s1 : s0;
            v[k].z *= (r >= 3) ? s1 : s0;
            v[k].w *= (r >= 2) ? s1 : s0;
        }
    }

    #pragma unroll
    for (int k = 0; k < 4; k++)
        __stcs(reinterpret_cast<float4*>(op[k]), v[k]);
}

extern "C" void kernel_launch(void* const* d_in, const int* in_sizes, int n_in,
                              void* d_out, int out_size) {
    const float* in = (const float*)d_in[0];
    float* out = (float*)d_out;

    int n_rows = in_sizes[0] / IN_W;      // 65536 (divisible by 4)
    int rowsQ  = n_rows / 4;
    int quarter4 = rowsQ * OUT_W4;

    int threads = 256;
    int blocks = (quarter4 + threads - 1) / threads;
    gbp_kernel<<<blocks, threads>>>(in, out, quarter4, rowsQ);
}

// round 7
// speedup vs baseline: 1.0295x; 1.0295x over previous
#include <cuda_runtime.h>
#include <cstdint>

// GatedBlockParity: N x 2048 fp32 in -> N x 1664 fp32 out
// in row:  [0,256) scalars | [256,640) gates (384) | [640,1408) ns1 (256x3) | [1408,2048) ns2 (128x5)
// out row: [0,256) relu(scalars) | [256,1024) ns1*sig(g1) | [1024,1664) ns2*sig(g2)

static constexpr int IN_W   = 2048;
static constexpr int OUT_W  = 1664;
static constexpr int OUT_W4 = OUT_W / 4;   // 416 float4 per row = 13 warps exactly

__device__ __forceinline__ float sigmoidf_(float x) {
    return 1.0f / (1.0f + __expf(-x));
}

__device__ __forceinline__ float4 ldcs4(const float* p) {
    return __ldcs(reinterpret_cast<const float4*>(p));
}
__device__ __forceinline__ void stcs4(float* p, float4 v) {
    __stcs(reinterpret_cast<float4*>(p), v);
}

// R5 structure (2-row ILP, proven 141.4us) + streaming cache hints:
// read-once data and write-once stores use .cs (evict-first), so the
// multiply-re-read gate region [256,640) stays resident in L1/L2.
// Branch depends only on c -> identical for both rows (no divergence);
// the two LDG.128s issue back-to-back (MLP=2).
// Within one float4 of a period-p gated block, the 4 lanes touch exactly <=2
// distinct gates (i0=j/p, i0+1): load 2 gates, 2 sigmoids, select by r=j%p.
__global__ __launch_bounds__(256) void gbp_kernel(const float* __restrict__ in,
                                                  float* __restrict__ out,
                                                  int half4, int rowsHalf) {
    int idx = blockIdx.x * blockDim.x + threadIdx.x;
    if (idx >= half4) return;

    int row = idx / OUT_W4;
    int c4  = idx - row * OUT_W4;
    int c   = c4 << 2;

    const float* __restrict__ iA = in + (size_t)row * IN_W;
    const float* __restrict__ iB = iA + (size_t)rowsHalf * IN_W;
    float* __restrict__ oA = out + (size_t)row * OUT_W + c;
    float* __restrict__ oB = oA + (size_t)rowsHalf * OUT_W;

    float4 a, b;

    if (c < 256) {
        // scalars: relu
        a = ldcs4(iA + c);
        b = ldcs4(iB + c);
        a.x = fmaxf(a.x, 0.0f); a.y = fmaxf(a.y, 0.0f);
        a.z = fmaxf(a.z, 0.0f); a.w = fmaxf(a.w, 0.0f);
        b.x = fmaxf(b.x, 0.0f); b.y = fmaxf(b.y, 0.0f);
        b.z = fmaxf(b.z, 0.0f); b.w = fmaxf(b.w, 0.0f);
    } else if (c < 1024) {
        // ns1: 256 groups of 3, gated by g1 = in-row[256 + i]
        int j  = c - 256;
        a = ldcs4(iA + 640 + j);
        b = ldcs4(iB + 640 + j);
        int i0 = j / 3;
        int r  = j - 3 * i0;
        float sa0 = sigmoidf_(iA[256 + i0]);
        float sa1 = sigmoidf_(iA[256 + i0 + 1]);
        float sb0 = sigmoidf_(iB[256 + i0]);
        float sb1 = sigmoidf_(iB[256 + i0 + 1]);
        // lane gate idx: x->i0; y->i0+(r==2); z->i0+(r>=1); w->i0+1
        a.x *= sa0;                      b.x *= sb0;
        a.y *= (r == 2) ? sa1 : sa0;     b.y *= (r == 2) ? sb1 : sb0;
        a.z *= (r >= 1) ? sa1 : sa0;     b.z *= (r >= 1) ? sb1 : sb0;
        a.w *= sa1;                      b.w *= sb1;
    } else {
        // ns2: 128 groups of 5, gated by g2 = in-row[512 + i]
        int j  = c - 1024;
        a = ldcs4(iA + 1408 + j);
        b = ldcs4(iB + 1408 + j);
        int i0 = j / 5;
        int r  = j - 5 * i0;
        float sa0 = sigmoidf_(iA[512 + i0]);
        float sa1 = sigmoidf_(iA[512 + i0 + 1]);   // at i0=127 reads ns1[0]; provably unused (r<2)
        float sb0 = sigmoidf_(iB[512 + i0]);
        float sb1 = sigmoidf_(iB[512 + i0 + 1]);
        // lane gate idx: x->i0; y->i0+(r==4); z->i0+(r>=3); w->i0+(r>=2)
        a.x *= sa0;                      b.x *= sb0;
        a.y *= (r == 4) ? sa1 : sa0;     b.y *= (r == 4) ? sb1 : sb0;
        a.z *= (r >= 3) ? sa1 : sa0;     b.z *= (r >= 3) ? sb1 : sb0;
        a.w *= (r >= 2) ? sa1 : sa0;     b.w *= (r >= 2) ? sb1 : sb0;
    }

    stcs4(oA, a);
    stcs4(oB, b);
}

extern "C" void kernel_launch(void* const* d_in, const int* in_sizes, int n_in,
                              void* d_out, int out_size) {
    const float* in = (const float*)d_in[0];
    float* out = (float*)d_out;

    int n_rows   = in_sizes[0] / IN_W;      // 65536 (even)
    int rowsHalf = n_rows / 2;
    int half4    = rowsHalf * OUT_W4;

    int threads = 256;
    int blocks = (half4 + threads - 1) / threads;
    gbp_kernel<<<blocks, threads>>>(in, out, half4, rowsHalf);
}

// round 9
// speedup vs baseline: 1.0887x; 1.0575x over previous
#include <cuda_runtime.h>
#include <cstdint>

// GatedBlockParity: N x 2048 fp32 in -> N x 1664 fp32 out
// in row:  [0,256) scalars | [256,640) gates (384) | [640,1408) ns1 (256x3) | [1408,2048) ns2 (128x5)
// out row: [0,256) relu(scalars) | [256,1024) ns1*sig(g1) | [1024,1664) ns2*sig(g2)

static constexpr int IN_W   = 2048;
static constexpr int OUT_W  = 1664;
static constexpr int OUT_W4 = OUT_W / 4;   // 416 float4 per row -> one thread each

__device__ __forceinline__ float sigmoidf_(float x) {
    return 1.0f / (1.0f + __expf(-x));
}

// One 416-thread block per row PAIR (row r and r+rowsHalf).
// threadIdx.x == c4 directly: no division, no bounds check, and the region
// boundaries (c4=64, c4=256) are warp-aligned -> zero divergence.
// Gates are loaded cooperatively with coalesced float4 LDGs into smem and
// sigmoided ONCE; consumers then do a single LDS each -> short store chain,
// no scattered scalar LDGs.
__global__ __launch_bounds__(416) void gbp_kernel(const float* __restrict__ in,
                                                  float* __restrict__ out,
                                                  int rowsHalf) {
    // [0,384): sigmoid(gates row A); [384,768): row B; +8 pad for the
    // provably-unused i0+1 overread at the last ns2 group.
    __shared__ float sg[776];

    int row = blockIdx.x;
    int tid = threadIdx.x;
    int c   = tid << 2;

    const float* __restrict__ iA = in + (size_t)row * IN_W;
    const float* __restrict__ iB = iA + (size_t)rowsHalf * IN_W;
    float* __restrict__ oA = out + (size_t)row * OUT_W + c;
    float* __restrict__ oB = oA + (size_t)rowsHalf * OUT_W;

    // Region-dependent input offset (warp-uniform branch).
    int off;
    if (c < 256)       off = c;                   // scalars
    else if (c < 1024) off = 640  + (c - 256);    // ns1 data
    else               off = 1408 + (c - 1024);   // ns2 data

    // Issue the streaming data loads first; their latency overlaps the
    // whole gate phase below.
    float4 a = *reinterpret_cast<const float4*>(iA + off);
    float4 b = *reinterpret_cast<const float4*>(iB + off);

    // Cooperative coalesced gate fill: 2 rows x 384 floats = 192 float4.
    if (tid < 96) {
        *reinterpret_cast<float4*>(&sg[tid << 2]) =
            *reinterpret_cast<const float4*>(iA + 256 + (tid << 2));
    } else if (tid < 192) {
        int t = tid - 96;
        *reinterpret_cast<float4*>(&sg[384 + (t << 2)]) =
            *reinterpret_cast<const float4*>(iB + 256 + (t << 2));
    }
    __syncthreads();

    // Sigmoid each gate exactly once (768 values, threads 0..383 do 2 each).
    if (tid < 384) {
        int k = tid << 1;
        sg[k]     = sigmoidf_(sg[k]);
        sg[k + 1] = sigmoidf_(sg[k + 1]);
    }
    __syncthreads();

    if (c < 256) {
        // scalars: relu
        a.x = fmaxf(a.x, 0.0f); a.y = fmaxf(a.y, 0.0f);
        a.z = fmaxf(a.z, 0.0f); a.w = fmaxf(a.w, 0.0f);
        b.x = fmaxf(b.x, 0.0f); b.y = fmaxf(b.y, 0.0f);
        b.z = fmaxf(b.z, 0.0f); b.w = fmaxf(b.w, 0.0f);
    } else if (c < 1024) {
        // ns1: 256 groups of 3; gate i0=j/3, i0+1 (<=2 distinct per float4)
        int j  = c - 256;
        int i0 = j / 3;
        int r  = j - 3 * i0;
        float sa0 = sg[i0],       sa1 = sg[i0 + 1];
        float sb0 = sg[384 + i0], sb1 = sg[384 + i0 + 1];
        // lane gate idx: x->i0; y->i0+(r==2); z->i0+(r>=1); w->i0+1
        a.x *= sa0;                      b.x *= sb0;
        a.y *= (r == 2) ? sa1 : sa0;     b.y *= (r == 2) ? sb1 : sb0;
        a.z *= (r >= 1) ? sa1 : sa0;     b.z *= (r >= 1) ? sb1 : sb0;
        a.w *= sa1;                      b.w *= sb1;
    } else {
        // ns2: 128 groups of 5; gates live at sg[256+i] (A), sg[640+i] (B)
        int j  = c - 1024;
        int i0 = j / 5;
        int r  = j - 5 * i0;
        float sa0 = sg[256 + i0], sa1 = sg[256 + i0 + 1]; // i0=127 -> sg[384], unused (r<2)
        float sb0 = sg[640 + i0], sb1 = sg[640 + i0 + 1]; // i0=127 -> sg[768] pad, unused
        // lane gate idx: x->i0; y->i0+(r==4); z->i0+(r>=3); w->i0+(r>=2)
        a.x *= sa0;                      b.x *= sb0;
        a.y *= (r == 4) ? sa1 : sa0;     b.y *= (r == 4) ? sb1 : sb0;
        a.z *= (r >= 3) ? sa1 : sa0;     b.z *= (r >= 3) ? sb1 : sb0;
        a.w *= (r >= 2) ? sa1 : sa0;     b.w *= (r >= 2) ? sb1 : sb0;
    }

    *reinterpret_cast<float4*>(oA) = a;
    *reinterpret_cast<float4*>(oB) = b;
}

extern "C" void kernel_launch(void* const* d_in, const int* in_sizes, int n_in,
                              void* d_out, int out_size) {
    const float* in = (const float*)d_in[0];
    float* out = (float*)d_out;

    int n_rows   = in_sizes[0] / IN_W;      // 65536 (even)
    int rowsHalf = n_rows / 2;

    gbp_kernel<<<rowsHalf, OUT_W4>>>(in, out, rowsHalf);
}